// round 1
// baseline (speedup 1.0000x reference)
#include <cuda_runtime.h>
#include <math.h>

#define BATCH 4
#define SEQ   2048
#define HID   768
#define NQKV  (3*HID)

// Scratch (device globals: allocation-free, graph-capturable)
__device__ float g_qkv[(size_t)BATCH * SEQ * NQKV];     // 75.5 MB: [b*s, 2304] = Q|K|V
__device__ float g_scores[(size_t)BATCH * SEQ * SEQ];   // 67 MB:  [b, q, k]

// ---------------------------------------------------------------------------
// Generic tiled SGEMM.
//   TRANSB=true : C = alpha * A (MxK, lda) * B^T (NxK, ldb)  [+ bias]
//   TRANSB=false: C = alpha * A (MxK, lda) * B   (KxN, ldb)  [+ bias]
// BM=BN=128, BK=16, 256 threads, 8x8 per-thread fragment. All problem dims
// here divide the tile sizes exactly, so no bounds checks.
// ---------------------------------------------------------------------------
template<bool TRANSB>
__global__ __launch_bounds__(256, 2)
void gemm_kernel(const float* __restrict__ A, const float* __restrict__ B,
                 const float* __restrict__ bias, float* __restrict__ C,
                 int lda, int ldb, int ldc, int K,
                 long long sA, long long sB, long long sC, float alpha)
{
    constexpr int BM = 128, BN = 128, BK = 16;
    __shared__ float As[BK][BM + 4];
    __shared__ float Bs[BK][BN + 4];

    const int tid = threadIdx.x;        // 0..255
    const int tx  = tid & 15;           // 0..15 -> N
    const int ty  = tid >> 4;           // 0..15 -> M

    const float* Ab = A + (long long)blockIdx.z * sA + (long long)blockIdx.y * BM * lda;
    const float* Bb = B + (long long)blockIdx.z * sB +
                      (TRANSB ? (long long)blockIdx.x * BN * ldb
                              : (long long)blockIdx.x * BN);
    float* Cb = C + (long long)blockIdx.z * sC + (long long)blockIdx.y * BM * ldc
                  + (long long)blockIdx.x * BN;

    float acc[8][8];
    #pragma unroll
    for (int i = 0; i < 8; i++)
        #pragma unroll
        for (int j = 0; j < 8; j++) acc[i][j] = 0.f;

    for (int k0 = 0; k0 < K; k0 += BK) {
        // --- A tile: 128 rows x 16 k, K-contiguous; transpose-store to As[k][m]
        #pragma unroll
        for (int i = 0; i < 2; i++) {
            int idx = tid + i * 256;            // 0..511 float4 slots
            int row = idx >> 2;
            int kc  = (idx & 3) << 2;
            float4 v = *reinterpret_cast<const float4*>(Ab + (long long)row * lda + k0 + kc);
            As[kc + 0][row] = v.x; As[kc + 1][row] = v.y;
            As[kc + 2][row] = v.z; As[kc + 3][row] = v.w;
        }
        if (TRANSB) {
            // B is NxK, K-contiguous; transpose-store to Bs[k][n]
            #pragma unroll
            for (int i = 0; i < 2; i++) {
                int idx = tid + i * 256;
                int row = idx >> 2;
                int kc  = (idx & 3) << 2;
                float4 v = *reinterpret_cast<const float4*>(Bb + (long long)row * ldb + k0 + kc);
                Bs[kc + 0][row] = v.x; Bs[kc + 1][row] = v.y;
                Bs[kc + 2][row] = v.z; Bs[kc + 3][row] = v.w;
            }
        } else {
            // B is KxN, N-contiguous; direct store Bs[k][n]
            #pragma unroll
            for (int i = 0; i < 2; i++) {
                int idx = tid + i * 256;
                int kr = idx >> 5;              // 0..15
                int nc = (idx & 31) << 2;       // 0..124
                *reinterpret_cast<float4*>(&Bs[kr][nc]) =
                    *reinterpret_cast<const float4*>(Bb + (long long)(k0 + kr) * ldb + nc);
            }
        }
        __syncthreads();

        #pragma unroll
        for (int kk = 0; kk < BK; kk++) {
            float a[8], bb[8];
            *reinterpret_cast<float4*>(&a[0])  = *reinterpret_cast<const float4*>(&As[kk][ty * 4]);
            *reinterpret_cast<float4*>(&a[4])  = *reinterpret_cast<const float4*>(&As[kk][ty * 4 + 64]);
            *reinterpret_cast<float4*>(&bb[0]) = *reinterpret_cast<const float4*>(&Bs[kk][tx * 4]);
            *reinterpret_cast<float4*>(&bb[4]) = *reinterpret_cast<const float4*>(&Bs[kk][tx * 4 + 64]);
            #pragma unroll
            for (int i = 0; i < 8; i++)
                #pragma unroll
                for (int j = 0; j < 8; j++)
                    acc[i][j] = fmaf(a[i], bb[j], acc[i][j]);
        }
        __syncthreads();
    }

    // epilogue: alpha, optional bias (per output column), float4 stores
    float bv[8];
    #pragma unroll
    for (int jh = 0; jh < 2; jh++)
        #pragma unroll
        for (int jj = 0; jj < 4; jj++) {
            int c = blockIdx.x * BN + tx * 4 + jh * 64 + jj;
            bv[jh * 4 + jj] = bias ? bias[c] : 0.f;
        }

    #pragma unroll
    for (int ih = 0; ih < 2; ih++)
        #pragma unroll
        for (int ii = 0; ii < 4; ii++) {
            int r = ty * 4 + ih * 64 + ii;
            #pragma unroll
            for (int jh = 0; jh < 2; jh++) {
                float4 o;
                o.x = alpha * acc[ih * 4 + ii][jh * 4 + 0] + bv[jh * 4 + 0];
                o.y = alpha * acc[ih * 4 + ii][jh * 4 + 1] + bv[jh * 4 + 1];
                o.z = alpha * acc[ih * 4 + ii][jh * 4 + 2] + bv[jh * 4 + 2];
                o.w = alpha * acc[ih * 4 + ii][jh * 4 + 3] + bv[jh * 4 + 3];
                *reinterpret_cast<float4*>(Cb + (long long)r * ldc + tx * 4 + jh * 64) = o;
            }
        }
}

// ---------------------------------------------------------------------------
// Row softmax over SEQ=2048, one block (256 threads) per row, single pass,
// values kept in registers (8 per thread).
// ---------------------------------------------------------------------------
__global__ __launch_bounds__(256)
void softmax_kernel(float* __restrict__ S)
{
    __shared__ float red[8];
    float* p = S + (size_t)blockIdx.x * SEQ;
    const int tid = threadIdx.x;

    float v[8];
    float mx = -1e30f;
    #pragma unroll
    for (int i = 0; i < 8; i++) {
        v[i] = p[tid + i * 256];
        mx = fmaxf(mx, v[i]);
    }
    #pragma unroll
    for (int o = 16; o; o >>= 1) mx = fmaxf(mx, __shfl_xor_sync(0xffffffffu, mx, o));
    if ((tid & 31) == 0) red[tid >> 5] = mx;
    __syncthreads();
    mx = fmaxf(fmaxf(fmaxf(red[0], red[1]), fmaxf(red[2], red[3])),
               fmaxf(fmaxf(red[4], red[5]), fmaxf(red[6], red[7])));

    float sum = 0.f;
    #pragma unroll
    for (int i = 0; i < 8; i++) { v[i] = expf(v[i] - mx); sum += v[i]; }
    #pragma unroll
    for (int o = 16; o; o >>= 1) sum += __shfl_xor_sync(0xffffffffu, sum, o);
    __syncthreads();                       // red[] reuse
    if ((tid & 31) == 0) red[tid >> 5] = sum;
    __syncthreads();
    sum = red[0] + red[1] + red[2] + red[3] + red[4] + red[5] + red[6] + red[7];

    float inv = 1.f / sum;
    #pragma unroll
    for (int i = 0; i < 8; i++) p[tid + i * 256] = v[i] * inv;
}

// ---------------------------------------------------------------------------
extern "C" void kernel_launch(void* const* d_in, const int* in_sizes, int n_in,
                              void* d_out, int out_size)
{
    const float* X = (const float*)d_in[0];   // [4,2048,768]
    const float* W = (const float*)d_in[1];   // [2304,768]
    const float* b = (const float*)d_in[2];   // [2304]
    float* out = (float*)d_out;               // [4,2048,768]

    void* p0; cudaGetSymbolAddress(&p0, g_qkv);
    void* p1; cudaGetSymbolAddress(&p1, g_scores);
    float* qkv = (float*)p0;
    float* sc  = (float*)p1;

    // 1) QKV = X @ W^T + b : M=8192, N=2304, K=768
    gemm_kernel<true><<<dim3(NQKV / 128, (BATCH * SEQ) / 128, 1), 256>>>(
        X, W, b, qkv,
        HID, HID, NQKV, HID,
        0LL, 0LL, 0LL, 1.0f);

    // 2) scores = (Q @ K^T) / sqrt(768) per batch : M=N=2048, K=768
    gemm_kernel<true><<<dim3(SEQ / 128, SEQ / 128, BATCH), 256>>>(
        qkv /*Q*/, qkv + HID /*K*/, nullptr, sc,
        NQKV, NQKV, SEQ, HID,
        (long long)SEQ * NQKV, (long long)SEQ * NQKV, (long long)SEQ * SEQ,
        1.0f / sqrtf((float)HID));

    // 3) row softmax
    softmax_kernel<<<BATCH * SEQ, 256>>>(sc);

    // 4) out = attn @ V per batch : M=2048, N=768, K=2048
    gemm_kernel<false><<<dim3(HID / 128, SEQ / 128, BATCH), 256>>>(
        sc, qkv + 2 * HID /*V*/, nullptr, out,
        SEQ, NQKV, HID, SEQ,
        (long long)SEQ * SEQ, (long long)SEQ * NQKV, (long long)SEQ * HID,
        1.0f);
}

// round 3
// speedup vs baseline: 2.0980x; 2.0980x over previous
#include <cuda_runtime.h>
#include <cuda_bf16.h>
#include <cstdint>
#include <math.h>

#define BATCH 4
#define SEQ   2048
#define HID   768
#define NQKV  (3*HID)
#define TOK   (BATCH*SEQ)   // 8192

// ---------------- scratch (device globals; allocation-free) ----------------
__device__ __align__(128) __nv_bfloat16 g_xhi[(size_t)TOK*HID],  g_xlo[(size_t)TOK*HID];
__device__ __align__(128) __nv_bfloat16 g_whi[(size_t)NQKV*HID], g_wlo[(size_t)NQKV*HID];
__device__ __align__(128) __nv_bfloat16 g_qhi[(size_t)TOK*HID],  g_qlo[(size_t)TOK*HID];
__device__ __align__(128) __nv_bfloat16 g_khi[(size_t)TOK*HID],  g_klo[(size_t)TOK*HID];
__device__ __align__(128) __nv_bfloat16 g_vThi[(size_t)BATCH*HID*SEQ], g_vTlo[(size_t)BATCH*HID*SEQ];
__device__ __align__(128) float         g_scores[(size_t)BATCH*SEQ*SEQ];
__device__ __align__(128) __nv_bfloat16 g_phi[(size_t)BATCH*SEQ*SEQ], g_plo[(size_t)BATCH*SEQ*SEQ];

// ---------------- PTX helpers (sm_80-compatible only) ----------------
__device__ __forceinline__ uint32_t smem_u32(const void* p) {
    uint32_t a;
    asm("{ .reg .u64 t; cvta.to.shared.u64 t, %1; cvt.u32.u64 %0, t; }" : "=r"(a) : "l"(p));
    return a;
}
__device__ __forceinline__ void cp16(uint32_t dst, const void* src) {
    asm volatile("cp.async.cg.shared.global [%0], [%1], 16;" :: "r"(dst), "l"(src));
}
#define CP_COMMIT() asm volatile("cp.async.commit_group;" ::: "memory")
#define CP_WAIT1()  asm volatile("cp.async.wait_group 1;" ::: "memory")

__device__ __forceinline__ void ldm4(uint32_t* r, uint32_t addr) {
    asm volatile("ldmatrix.sync.aligned.m8n8.x4.shared.b16 {%0,%1,%2,%3}, [%4];"
                 : "=r"(r[0]), "=r"(r[1]), "=r"(r[2]), "=r"(r[3]) : "r"(addr));
}
__device__ __forceinline__ void mma16816(float* c, const uint32_t* a, const uint32_t* b) {
    asm volatile("mma.sync.aligned.m16n8k16.row.col.f32.bf16.bf16.f32 "
                 "{%0,%1,%2,%3}, {%4,%5,%6,%7}, {%8,%9}, {%0,%1,%2,%3};"
                 : "+f"(c[0]), "+f"(c[1]), "+f"(c[2]), "+f"(c[3])
                 : "r"(a[0]), "r"(a[1]), "r"(a[2]), "r"(a[3]), "r"(b[0]), "r"(b[1]));
}

// ---------------- HMMA GEMM: C[128x128] = 3-term split A(MxK)·B(NxK)^T ------
// SMEM tile: 128 rows x 32 bf16 padded to 80B/row (conflict-free ldmatrix).
#define ROWB    80
#define TILE_B  (128*ROWB)          // 10240
#define STAGE_B (4*TILE_B)          // 40960
#define NSTAGE  3
#define SM_TOTAL (NSTAGE*STAGE_B)   // 122880

// EPI: 0 = QKV (bias, split->q/k hi/lo + transposed V), 1 = scores f32*alpha, 2 = out f32
template<int EPI>
__global__ __launch_bounds__(256, 1)
void hmma_gemm(const __nv_bfloat16* __restrict__ Ahi, const __nv_bfloat16* __restrict__ Alo,
               const __nv_bfloat16* __restrict__ Bhi, const __nv_bfloat16* __restrict__ Blo,
               long long lda, long long ldb, int K,
               long long sA, long long sB,
               const float* __restrict__ bias, float alpha,
               float* __restrict__ Cf, long long ldc, long long sC)
{
    extern __shared__ char smem[];
    const uint32_t sbase = smem_u32(smem);
    const int tid = threadIdx.x;
    const int bx = blockIdx.x, by = blockIdx.y, bz = blockIdx.z;
    const int wid = tid >> 5, lane = tid & 31;
    const int wm = wid & 1;          // 2 warps in M (64 rows each)
    const int wn = wid >> 1;         // 4 warps in N (32 cols each)

    const __nv_bfloat16* a_hi = Ahi + bz * sA + (long long)by * 128 * lda;
    const __nv_bfloat16* a_lo = Alo + bz * sA + (long long)by * 128 * lda;
    const __nv_bfloat16* b_hi = Bhi + bz * sB + (long long)bx * 128 * ldb;
    const __nv_bfloat16* b_lo = Blo + bz * sB + (long long)bx * 128 * ldb;

    // per-thread ldmatrix lane addressing
    const int m_in = (lane & 7) + 8 * ((lane >> 3) & 1);
    const int kb_a = (lane >> 4) * 16;
    const int n_in = (lane & 7) + 8 * (lane >> 4);
    const int kb_b = ((lane >> 3) & 1) * 16;
    const uint32_t a_row_off = (uint32_t)((wm * 64 + m_in) * ROWB + kb_a);
    const uint32_t b_row_off = (uint32_t)((wn * 32 + n_in) * ROWB + kb_b);

    float acc[4][4][4];
    #pragma unroll
    for (int i = 0; i < 4; i++)
        #pragma unroll
        for (int j = 0; j < 4; j++)
            #pragma unroll
            for (int r = 0; r < 4; r++) acc[i][j][r] = 0.f;

    const int nch = K / 32;

    // stage loader: tile t constant, 2 tasks/thread/tile
    auto load_stage = [&](int c, int slot) {
        const uint32_t dbase = sbase + (uint32_t)slot * STAGE_B;
        const long long k0 = (long long)c * 32;
        #pragma unroll
        for (int t = 0; t < 4; t++) {
            const __nv_bfloat16* src = (t == 0) ? a_hi : (t == 1) ? a_lo : (t == 2) ? b_hi : b_lo;
            const long long ld = (t < 2) ? lda : ldb;
            #pragma unroll
            for (int p = 0; p < 2; p++) {
                int idx = tid + p * 256;        // 0..511
                int r = idx >> 2, ch = idx & 3;
                cp16(dbase + (uint32_t)(t * TILE_B + r * ROWB + ch * 16),
                     src + (long long)r * ld + k0 + ch * 8);
            }
        }
    };

    load_stage(0, 0); CP_COMMIT();
    load_stage(1, 1); CP_COMMIT();

    for (int c = 0; c < nch; c++) {
        CP_WAIT1();
        __syncthreads();
        if (c + 2 < nch) load_stage(c + 2, (c + 2) % NSTAGE);
        CP_COMMIT();

        const uint32_t st = sbase + (uint32_t)(c % NSTAGE) * STAGE_B;
        #pragma unroll
        for (int ks = 0; ks < 2; ks++) {
            uint32_t ah[4][4], al[4][4], bh[2][4], bl[2][4];
            #pragma unroll
            for (int mi = 0; mi < 4; mi++) {
                uint32_t ao = st + a_row_off + (uint32_t)(mi * 16 * ROWB + ks * 32);
                ldm4(ah[mi], ao);
                ldm4(al[mi], ao + TILE_B);
            }
            #pragma unroll
            for (int nj = 0; nj < 2; nj++) {
                uint32_t bo = st + 2 * TILE_B + b_row_off + (uint32_t)(nj * 16 * ROWB + ks * 32);
                ldm4(bh[nj], bo);
                ldm4(bl[nj], bo + TILE_B);
            }
            #pragma unroll
            for (int mi = 0; mi < 4; mi++)
                #pragma unroll
                for (int ni = 0; ni < 4; ni++) {
                    const uint32_t* bph = &bh[ni >> 1][(ni & 1) * 2];
                    const uint32_t* bpl = &bl[ni >> 1][(ni & 1) * 2];
                    mma16816(acc[mi][ni], ah[mi], bph);
                    mma16816(acc[mi][ni], ah[mi], bpl);
                    mma16816(acc[mi][ni], al[mi], bph);
                }
        }
    }

    // ---------------- epilogue ----------------
    const int g = lane >> 2, t4 = lane & 3;
    const int row0 = by * 128 + wm * 64 + g;
    const int col0 = bx * 128 + wn * 32 + t4 * 2;

    if (EPI == 0) {
        const int seg = (bx * 128) / HID;          // 0=Q, 1=K, 2=V (tile never straddles)
        #pragma unroll
        for (int mi = 0; mi < 4; mi++)
            #pragma unroll
            for (int ni = 0; ni < 4; ni++)
                #pragma unroll
                for (int h = 0; h < 2; h++) {      // h: row halves (regs {0,1} vs {2,3})
                    long long row = row0 + mi * 16 + h * 8;
                    int col = col0 + ni * 8;
                    float v0 = acc[mi][ni][h * 2 + 0] + bias[col];
                    float v1 = acc[mi][ni][h * 2 + 1] + bias[col + 1];
                    __nv_bfloat16 h0 = __float2bfloat16(v0);
                    __nv_bfloat16 h1 = __float2bfloat16(v1);
                    __nv_bfloat16 l0 = __float2bfloat16(v0 - __bfloat162float(h0));
                    __nv_bfloat16 l1 = __float2bfloat16(v1 - __bfloat162float(h1));
                    if (seg < 2) {
                        int cc = col - seg * HID;
                        __nv_bfloat16* dh = (seg == 0) ? g_qhi : g_khi;
                        __nv_bfloat16* dl = (seg == 0) ? g_qlo : g_klo;
                        *reinterpret_cast<__nv_bfloat162*>(dh + row * HID + cc) = __nv_bfloat162(h0, h1);
                        *reinterpret_cast<__nv_bfloat162*>(dl + row * HID + cc) = __nv_bfloat162(l0, l1);
                    } else {
                        int hh = col - 2 * HID;
                        int b = (int)(row >> 11), s = (int)(row & 2047);
                        size_t o0 = ((size_t)b * HID + hh) * SEQ + s;
                        size_t o1 = o0 + SEQ;      // next head
                        g_vThi[o0] = h0; g_vTlo[o0] = l0;
                        g_vThi[o1] = h1; g_vTlo[o1] = l1;
                    }
                }
    } else {
        float* cb = Cf + bz * sC;
        #pragma unroll
        for (int mi = 0; mi < 4; mi++)
            #pragma unroll
            for (int ni = 0; ni < 4; ni++)
                #pragma unroll
                for (int h = 0; h < 2; h++) {
                    long long row = row0 + mi * 16 + h * 8;
                    int col = col0 + ni * 8;
                    float2 o;
                    o.x = alpha * acc[mi][ni][h * 2 + 0];
                    o.y = alpha * acc[mi][ni][h * 2 + 1];
                    *reinterpret_cast<float2*>(cb + row * ldc + col) = o;
                }
    }
}

// ---------------- fp32 -> bf16 hi/lo split ----------------
__global__ __launch_bounds__(256)
void split_f32(const float* __restrict__ x, __nv_bfloat16* __restrict__ hi,
               __nv_bfloat16* __restrict__ lo, int n4)
{
    int i = blockIdx.x * 256 + threadIdx.x;
    if (i >= n4) return;
    float4 v = reinterpret_cast<const float4*>(x)[i];
    __nv_bfloat16 h0 = __float2bfloat16(v.x), h1 = __float2bfloat16(v.y);
    __nv_bfloat16 h2 = __float2bfloat16(v.z), h3 = __float2bfloat16(v.w);
    __nv_bfloat16 l0 = __float2bfloat16(v.x - __bfloat162float(h0));
    __nv_bfloat16 l1 = __float2bfloat16(v.y - __bfloat162float(h1));
    __nv_bfloat16 l2 = __float2bfloat16(v.z - __bfloat162float(h2));
    __nv_bfloat16 l3 = __float2bfloat16(v.w - __bfloat162float(h3));
    reinterpret_cast<__nv_bfloat162*>(hi)[2*i]   = __nv_bfloat162(h0, h1);
    reinterpret_cast<__nv_bfloat162*>(hi)[2*i+1] = __nv_bfloat162(h2, h3);
    reinterpret_cast<__nv_bfloat162*>(lo)[2*i]   = __nv_bfloat162(l0, l1);
    reinterpret_cast<__nv_bfloat162*>(lo)[2*i+1] = __nv_bfloat162(l2, l3);
}

// ---------------- softmax: fp32 scores -> bf16 hi/lo probs ----------------
__global__ __launch_bounds__(256)
void softmax_kernel(const float* __restrict__ S, __nv_bfloat16* __restrict__ Phi,
                    __nv_bfloat16* __restrict__ Plo)
{
    __shared__ float red[8];
    const float* p = S + (size_t)blockIdx.x * SEQ;
    const int tid = threadIdx.x;

    float v[8];
    float mx = -1e30f;
    #pragma unroll
    for (int i = 0; i < 8; i++) { v[i] = p[tid + i * 256]; mx = fmaxf(mx, v[i]); }
    #pragma unroll
    for (int o = 16; o; o >>= 1) mx = fmaxf(mx, __shfl_xor_sync(0xffffffffu, mx, o));
    if ((tid & 31) == 0) red[tid >> 5] = mx;
    __syncthreads();
    mx = fmaxf(fmaxf(fmaxf(red[0], red[1]), fmaxf(red[2], red[3])),
               fmaxf(fmaxf(red[4], red[5]), fmaxf(red[6], red[7])));

    float sum = 0.f;
    #pragma unroll
    for (int i = 0; i < 8; i++) { v[i] = expf(v[i] - mx); sum += v[i]; }
    #pragma unroll
    for (int o = 16; o; o >>= 1) sum += __shfl_xor_sync(0xffffffffu, sum, o);
    __syncthreads();
    if ((tid & 31) == 0) red[tid >> 5] = sum;
    __syncthreads();
    sum = red[0] + red[1] + red[2] + red[3] + red[4] + red[5] + red[6] + red[7];

    float inv = 1.f / sum;
    __nv_bfloat16* ph = Phi + (size_t)blockIdx.x * SEQ;
    __nv_bfloat16* pl = Plo + (size_t)blockIdx.x * SEQ;
    #pragma unroll
    for (int i = 0; i < 8; i++) {
        float w = v[i] * inv;
        __nv_bfloat16 h = __float2bfloat16(w);
        __nv_bfloat16 l = __float2bfloat16(w - __bfloat162float(h));
        ph[tid + i * 256] = h;
        pl[tid + i * 256] = l;
    }
}

// ---------------------------------------------------------------------------
extern "C" void kernel_launch(void* const* d_in, const int* in_sizes, int n_in,
                              void* d_out, int out_size)
{
    const float* X = (const float*)d_in[0];
    const float* W = (const float*)d_in[1];
    const float* b = (const float*)d_in[2];
    float* out = (float*)d_out;

    static bool attr_set = false;
    if (!attr_set) {
        cudaFuncSetAttribute(hmma_gemm<0>, cudaFuncAttributeMaxDynamicSharedMemorySize, SM_TOTAL);
        cudaFuncSetAttribute(hmma_gemm<1>, cudaFuncAttributeMaxDynamicSharedMemorySize, SM_TOTAL);
        cudaFuncSetAttribute(hmma_gemm<2>, cudaFuncAttributeMaxDynamicSharedMemorySize, SM_TOTAL);
        attr_set = true;
    }

    void *xhi, *xlo, *whi, *wlo, *qhi, *qlo, *khi, *klo, *vThi, *vTlo, *sc, *phi, *plo;
    cudaGetSymbolAddress(&xhi, g_xhi);   cudaGetSymbolAddress(&xlo, g_xlo);
    cudaGetSymbolAddress(&whi, g_whi);   cudaGetSymbolAddress(&wlo, g_wlo);
    cudaGetSymbolAddress(&qhi, g_qhi);   cudaGetSymbolAddress(&qlo, g_qlo);
    cudaGetSymbolAddress(&khi, g_khi);   cudaGetSymbolAddress(&klo, g_klo);
    cudaGetSymbolAddress(&vThi, g_vThi); cudaGetSymbolAddress(&vTlo, g_vTlo);
    cudaGetSymbolAddress(&sc, g_scores);
    cudaGetSymbolAddress(&phi, g_phi);   cudaGetSymbolAddress(&plo, g_plo);

    // 1) split inputs to bf16 hi/lo
    split_f32<<<(TOK * HID / 4 + 255) / 256, 256>>>(X, (__nv_bfloat16*)xhi, (__nv_bfloat16*)xlo, TOK * HID / 4);
    split_f32<<<(NQKV * HID / 4 + 255) / 256, 256>>>(W, (__nv_bfloat16*)whi, (__nv_bfloat16*)wlo, NQKV * HID / 4);

    // 2) QKV = X @ W^T + b  (M=8192, N=2304, K=768) -> q/k hi/lo + vT hi/lo
    hmma_gemm<0><<<dim3(NQKV / 128, TOK / 128, 1), 256, SM_TOTAL>>>(
        (__nv_bfloat16*)xhi, (__nv_bfloat16*)xlo, (__nv_bfloat16*)whi, (__nv_bfloat16*)wlo,
        HID, HID, HID, 0LL, 0LL, b, 1.0f, nullptr, 0LL, 0LL);

    // 3) scores = (Q @ K^T) / sqrt(768)  per batch (M=N=2048, K=768)
    hmma_gemm<1><<<dim3(SEQ / 128, SEQ / 128, BATCH), 256, SM_TOTAL>>>(
        (__nv_bfloat16*)qhi, (__nv_bfloat16*)qlo, (__nv_bfloat16*)khi, (__nv_bfloat16*)klo,
        HID, HID, HID, (long long)SEQ * HID, (long long)SEQ * HID,
        nullptr, rsqrtf((float)HID), (float*)sc, SEQ, (long long)SEQ * SEQ);

    // 4) softmax -> bf16 hi/lo probs
    softmax_kernel<<<BATCH * SEQ, 256>>>((const float*)sc, (__nv_bfloat16*)phi, (__nv_bfloat16*)plo);

    // 5) out = P @ V  per batch (M=2048, N=768, K=2048); B = vT (NT layout)
    hmma_gemm<2><<<dim3(HID / 128, SEQ / 128, BATCH), 256, SM_TOTAL>>>(
        (__nv_bfloat16*)phi, (__nv_bfloat16*)plo, (__nv_bfloat16*)vThi, (__nv_bfloat16*)vTlo,
        SEQ, SEQ, SEQ, (long long)SEQ * SEQ, (long long)HID * SEQ,
        nullptr, 1.0f, out, HID, (long long)SEQ * HID);
}